// round 10
// baseline (speedup 1.0000x reference)
#include <cuda_runtime.h>

#define BATCH 4
#define C 256
#define H 256
#define W 256
#define S 8
#define HP 32
#define WP 32
#define N 1024     // HP*WP tokens
#define KC 32      // key channels

typedef unsigned int uint;

// m-permutation within each 8-group: logical l -> physical 2*(l&3) + (l>>2).
// Consumers then load logical (t, t+4) as adjacent physical (2t, 2t+1) -> LDS.64.

// ---------------- device scratch (no allocs allowed) ----------------
__device__ float g_xf[BATCH * C * N];        // pooled features  [b][c][n]
__device__ float g_qT[BATCH * N * KC];       // q transposed     [b][n][k]  (k perm)
__device__ float g_kT[BATCH * N * KC];       // k transposed     [b][m][k]  (k perm)
__device__ float g_v[BATCH * C * N];         // v                [b][c][m]  (m perm)
__device__ float g_attn[BATCH * N * N];      // exp(energy)      [b][n][m]  (m perm)
__device__ float g_rsum[BATCH * N];          // softmax row sums
__device__ float g_out[BATCH * C * N];       // attn output      [b][c][n]

__device__ __forceinline__ float to_tf32(float x) {
    float r; asm("cvt.rna.tf32.f32 %0, %1;" : "=f"(r) : "f"(x)); return r;
}

__device__ __forceinline__ void mma_tf32(float* d, const uint* a, const uint* b) {
    asm volatile(
        "mma.sync.aligned.m16n8k8.row.col.f32.tf32.tf32.f32 "
        "{%0,%1,%2,%3}, {%4,%5,%6,%7}, {%8,%9}, {%0,%1,%2,%3};"
        : "+f"(d[0]), "+f"(d[1]), "+f"(d[2]), "+f"(d[3])
        : "r"(a[0]), "r"(a[1]), "r"(a[2]), "r"(a[3]), "r"(b[0]), "r"(b[1]));
}

__device__ __forceinline__ void cp16(uint smem_addr, const void* gptr) {
    asm volatile("cp.async.ca.shared.global [%0], [%1], 16;"
                 :: "r"(smem_addr), "l"(gptr));
}

// FMA-pipe exp: exp(x) = 2^(x*log2e), magic-number round + deg-5 poly + exp-bit ldexp.
__device__ __forceinline__ float fast_expf(float x) {
    x = fmaxf(x, -80.0f);
    float y = x * 1.4426950408889634f;
    float z = y + 12582912.0f;
    int   e = __float_as_int(z);
    float n = z - 12582912.0f;
    float f = y - n;
    float p = 0.0013333558146428443f;
    p = fmaf(p, f, 0.009618129107628477f);
    p = fmaf(p, f, 0.05550410866482158f);
    p = fmaf(p, f, 0.2402265069591007f);
    p = fmaf(p, f, 0.6931471805599453f);
    p = fmaf(p, f, 1.0f);
    return __int_as_float(__float_as_int(p) + (e << 23));
}

// ---------------- kernel 1: 8x8 avg pool ----------------
__global__ void avgpool_kernel(const float* __restrict__ f) {
    int idx = blockIdx.x * blockDim.x + threadIdx.x;   // over BATCH*C*N
    int n  = idx & (N - 1);
    int bc = idx >> 10;
    int wp = n & (WP - 1);
    int hp = n >> 5;
    const float* src = f + ((size_t)bc * H + (size_t)hp * S) * W + (size_t)wp * S;
    float s = 0.f;
#pragma unroll
    for (int r = 0; r < S; r++) {
        float4 a = *(const float4*)(src + (size_t)r * W);
        float4 b = *(const float4*)(src + (size_t)r * W + 4);
        s += a.x + a.y + a.z + a.w + b.x + b.y + b.z + b.w;
    }
    g_xf[idx] = s * (1.f / 64.f);
}

// ---------------- kernel 2: q/k/v via tf32 HMMA ----------------
// rgroup 0: rows 0..31 = qw, 32..63 = kw -> qT/kT [token][kc] with kc PERMUTED.
// rgroup 1..4: vw rows -> g_v [c][m] with m (token) PERMUTED.
#define QLDA 36
#define QLDB 72
__global__ void qkv_mma_kernel(const float* __restrict__ qw, const float* __restrict__ qb,
                               const float* __restrict__ kw, const float* __restrict__ kb,
                               const float* __restrict__ vw, const float* __restrict__ vb) {
    int b  = blockIdx.z;
    int g  = blockIdx.y;
    int n0 = blockIdx.x * 64;

    __shared__ __align__(16) float As[2][64 * QLDA];   // A[m=64][k=32]
    __shared__ __align__(16) float Bs[2][32 * QLDB];   // B[k=32][n=64]
    __shared__ float bsh[64];

    int tid  = threadIdx.x;
    int lane = tid & 31, wid = tid >> 5;
    int wm = (wid & 1) * 32;
    int wn = (wid >> 1) * 16;
    int r4 = lane >> 2, q4 = lane & 3;

    int rowA0 = tid >> 3;          // 0..31
    int segA  = tid & 7;
    int rowB0 = tid >> 4;          // 0..15
    int segB  = tid & 15;

    const float* arow0;
    const float* arow1;
    int row1 = rowA0 + 32;
    if (g == 0) {
        arow0 = qw + (size_t)rowA0 * C;
        arow1 = kw + (size_t)(row1 - 32) * C;
    } else {
        arow0 = vw + (size_t)((g - 1) * 64 + rowA0) * C;
        arow1 = vw + (size_t)((g - 1) * 64 + row1) * C;
    }
    if (tid < 64) {
        float bv;
        if (g == 0) bv = (tid < 32) ? qb[tid] : kb[tid - 32];
        else        bv = vb[(g - 1) * 64 + tid];
        bsh[tid] = bv;
    }

    const float* xfb = g_xf + (size_t)b * C * N;

    float acc[2][2][4];
#pragma unroll
    for (int am = 0; am < 2; am++)
#pragma unroll
        for (int an = 0; an < 2; an++)
#pragma unroll
            for (int j = 0; j < 4; j++) acc[am][an][j] = 0.f;

    {
        cp16((uint)__cvta_generic_to_shared(&As[0][rowA0 * QLDA + segA * 4]), arow0 + segA * 4);
        cp16((uint)__cvta_generic_to_shared(&As[0][row1  * QLDA + segA * 4]), arow1 + segA * 4);
        cp16((uint)__cvta_generic_to_shared(&Bs[0][rowB0 * QLDB + segB * 4]),
             xfb + (size_t)rowB0 * N + n0 + segB * 4);
        cp16((uint)__cvta_generic_to_shared(&Bs[0][(rowB0 + 16) * QLDB + segB * 4]),
             xfb + (size_t)(rowB0 + 16) * N + n0 + segB * 4);
        asm volatile("cp.async.commit_group;");
    }

    for (int ch = 0; ch < 8; ch++) {          // C/32 = 8 chunks
        int s = ch & 1;
        if (ch + 1 < 8) {
            int c1 = (ch + 1) * 32;
            cp16((uint)__cvta_generic_to_shared(&As[s ^ 1][rowA0 * QLDA + segA * 4]), arow0 + c1 + segA * 4);
            cp16((uint)__cvta_generic_to_shared(&As[s ^ 1][row1  * QLDA + segA * 4]), arow1 + c1 + segA * 4);
            cp16((uint)__cvta_generic_to_shared(&Bs[s ^ 1][rowB0 * QLDB + segB * 4]),
                 xfb + (size_t)(c1 + rowB0) * N + n0 + segB * 4);
            cp16((uint)__cvta_generic_to_shared(&Bs[s ^ 1][(rowB0 + 16) * QLDB + segB * 4]),
                 xfb + (size_t)(c1 + rowB0 + 16) * N + n0 + segB * 4);
            asm volatile("cp.async.commit_group;");
            asm volatile("cp.async.wait_group 1;");
        } else {
            asm volatile("cp.async.wait_group 0;");
        }
        __syncthreads();

        const uint* Ass = (const uint*)As[s];
        const uint* Bss = (const uint*)Bs[s];
#pragma unroll
        for (int k8 = 0; k8 < 32; k8 += 8) {
            uint a[2][4], bb[2][2];
#pragma unroll
            for (int am = 0; am < 2; am++) {
                int base = (wm + am * 16 + r4) * QLDA + k8 + q4;
                a[am][0] = Ass[base];
                a[am][1] = Ass[base + 8 * QLDA];
                a[am][2] = Ass[base + 4];
                a[am][3] = Ass[base + 8 * QLDA + 4];
            }
#pragma unroll
            for (int an = 0; an < 2; an++) {
                int nb = wn + an * 8 + r4;
                bb[an][0] = Bss[(k8 + q4) * QLDB + nb];
                bb[an][1] = Bss[(k8 + q4 + 4) * QLDB + nb];
            }
#pragma unroll
            for (int am = 0; am < 2; am++)
#pragma unroll
                for (int an = 0; an < 2; an++)
                    mma_tf32(acc[am][an], a[am], bb[an]);
        }
        __syncthreads();
    }

    int cc = (lane & 3) * 2;
    int p0 = ((q4 & 1) << 2) | (q4 >> 1);   // physical offset of logical col 2*q4
    if (g == 0) {
        // qT/kT [token][kc], channel index PERMUTED within 8-groups
        float* QT = g_qT + (size_t)b * N * KC;
        float* KT = g_kT + (size_t)b * N * KC;
#pragma unroll
        for (int am = 0; am < 2; am++)
#pragma unroll
            for (int an = 0; an < 2; an++) {
                int r  = wm + am * 16 + r4;
                int nc = n0 + wn + an * 8 + cc;
#pragma unroll
                for (int dr = 0; dr < 2; dr++) {
                    int rr = r + dr * 8;
                    float d0 = acc[am][an][dr * 2 + 0] + bsh[rr];
                    float d1 = acc[am][an][dr * 2 + 1] + bsh[rr];
                    int ch_l = (rr < 32) ? rr : rr - 32;              // logical channel
                    int ch_p = (ch_l & ~7) | ((ch_l & 3) << 1) | ((ch_l & 4) >> 2);
                    float* dst = (rr < 32) ? (QT + ch_p) : (KT + ch_p);
                    dst[(size_t)nc * KC]       = to_tf32(d0);
                    dst[(size_t)(nc + 1) * KC] = to_tf32(d1);
                }
            }
    } else {
        // V [c][m], token column PERMUTED within 8-groups
        float* V = g_v + (size_t)b * C * N + (size_t)(g - 1) * 64 * N;
#pragma unroll
        for (int am = 0; am < 2; am++)
#pragma unroll
            for (int an = 0; an < 2; an++) {
                int r  = wm + am * 16 + r4;
                int nb = n0 + wn + an * 8;       // 8-group base (multiple of 8)
                float v00 = to_tf32(acc[am][an][0] + bsh[r]);
                float v01 = to_tf32(acc[am][an][1] + bsh[r]);
                float v10 = to_tf32(acc[am][an][2] + bsh[r + 8]);
                float v11 = to_tf32(acc[am][an][3] + bsh[r + 8]);
                V[(size_t)r * N + nb + p0]           = v00;
                V[(size_t)r * N + nb + p0 + 2]       = v01;
                V[(size_t)(r + 8) * N + nb + p0]     = v10;
                V[(size_t)(r + 8) * N + nb + p0 + 2] = v11;
            }
    }
}

// ---------------- kernel 3: energy via HMMA (perm-k LDS.64) + exp + row sums ----------------
#define ALD 40
__global__ void attn_mma_kernel() {
    int b  = blockIdx.y;
    int n0 = blockIdx.x * 16;
    int tid  = threadIdx.x;
    int lane = tid & 31, w = tid >> 5;
    int r4 = lane >> 2, q4 = lane & 3;

    __shared__ __align__(16) float Asm[16 * ALD];        // qT tile [16 n][32 k(perm)]
    __shared__ __align__(16) float Bs[2][128 * ALD];     // kT chunk [128 m][32 k(perm)]
    __shared__ float red[16][8];

    const float* QT = g_qT + (size_t)b * N * KC;
    const float* KT = g_kT + (size_t)b * N * KC;
    float* P = g_attn + (size_t)b * N * N;

    if (tid < 128) {
        int row = tid >> 3, seg = tid & 7;
        cp16((uint)__cvta_generic_to_shared(&Asm[row * ALD + seg * 4]),
             QT + (size_t)(n0 + row) * KC + seg * 4);
    }
    {
#pragma unroll
        for (int i = 0; i < 4; i++) {
            int slot = tid + i * 256;
            int rr = slot >> 3, ss = slot & 7;
            cp16((uint)__cvta_generic_to_shared(&Bs[0][rr * ALD + ss * 4]),
                 KT + (size_t)rr * KC + ss * 4);
        }
        asm volatile("cp.async.commit_group;");
    }

    uint a_all[4][4];
    float rs0 = 0.f, rs1 = 0.f;
    const float scale = 0.17677669529663687f;   // 32^-0.5
    int p0 = ((q4 & 1) << 2) | (q4 >> 1);       // physical m offset for logical 2*q4

    for (int ch = 0; ch < 8; ch++) {
        int s = ch & 1;
        if (ch + 1 < 8) {
            int m1 = (ch + 1) * 128;
#pragma unroll
            for (int i = 0; i < 4; i++) {
                int slot = tid + i * 256;
                int rr = slot >> 3, ss = slot & 7;
                cp16((uint)__cvta_generic_to_shared(&Bs[s ^ 1][rr * ALD + ss * 4]),
                     KT + (size_t)(m1 + rr) * KC + ss * 4);
            }
            asm volatile("cp.async.commit_group;");
            asm volatile("cp.async.wait_group 1;");
        } else {
            asm volatile("cp.async.wait_group 0;");
        }
        __syncthreads();

        if (ch == 0) {
            const uint* Au = (const uint*)Asm;
#pragma unroll
            for (int k8 = 0; k8 < 4; k8++) {
                uint2 a02 = *(const uint2*)&Au[r4 * ALD + k8 * 8 + 2 * q4];
                uint2 a13 = *(const uint2*)&Au[(r4 + 8) * ALD + k8 * 8 + 2 * q4];
                a_all[k8][0] = a02.x; a_all[k8][2] = a02.y;
                a_all[k8][1] = a13.x; a_all[k8][3] = a13.y;
            }
        }

        const uint* Bu = (const uint*)Bs[s];
        float acc[2][4];
#pragma unroll
        for (int at = 0; at < 2; at++)
#pragma unroll
            for (int j = 0; j < 4; j++) acc[at][j] = 0.f;

#pragma unroll
        for (int k8 = 0; k8 < 4; k8++) {
            uint bb[2][2];
#pragma unroll
            for (int at = 0; at < 2; at++) {
                uint2 bv = *(const uint2*)&Bu[(w * 16 + at * 8 + r4) * ALD + k8 * 8 + 2 * q4];
                bb[at][0] = bv.x;
                bb[at][1] = bv.y;
            }
#pragma unroll
            for (int at = 0; at < 2; at++)
                mma_tf32(acc[at], a_all[k8], bb[at]);
        }

        // exp + permuted store + row-sum accumulation
        int mbase = ch * 128 + w * 16;
#pragma unroll
        for (int at = 0; at < 2; at++) {
            float e0 = fast_expf(acc[at][0] * scale);
            float e1 = fast_expf(acc[at][1] * scale);
            float e2 = fast_expf(acc[at][2] * scale);
            float e3 = fast_expf(acc[at][3] * scale);
            rs0 += e0 + e1;
            rs1 += e2 + e3;
            int mb = mbase + at * 8;
            P[(size_t)(n0 + r4) * N + mb + p0]         = to_tf32(e0);
            P[(size_t)(n0 + r4) * N + mb + p0 + 2]     = to_tf32(e1);
            P[(size_t)(n0 + r4 + 8) * N + mb + p0]     = to_tf32(e2);
            P[(size_t)(n0 + r4 + 8) * N + mb + p0 + 2] = to_tf32(e3);
        }
        __syncthreads();
    }

    rs0 += __shfl_xor_sync(0xFFFFFFFFu, rs0, 1);
    rs0 += __shfl_xor_sync(0xFFFFFFFFu, rs0, 2);
    rs1 += __shfl_xor_sync(0xFFFFFFFFu, rs1, 1);
    rs1 += __shfl_xor_sync(0xFFFFFFFFu, rs1, 2);
    if (q4 == 0) { red[r4][w] = rs0; red[r4 + 8][w] = rs1; }
    __syncthreads();
    if (tid < 16) {
        float s = 0.f;
#pragma unroll
        for (int j = 0; j < 8; j++) s += red[tid][j];
        g_rsum[(size_t)b * N + n0 + tid] = s;
    }
}

// ---------------- kernel 4: out = v @ E^T (scaled by 1/rsum), perm-m LDS.64 ----------------
#define GBM 64
#define GBN 64
#define GBK 32
#define LDP 40   // r4*40 mod 32 = 8*r4 -> LDS.64 phases hit all 32 banks once
#define NCHUNK (N / GBK)
__global__ void out_gemm_kernel() {
    int b  = blockIdx.z;
    int c0 = blockIdx.y * GBM;
    int n0 = blockIdx.x * GBN;
    __shared__ __align__(16) uint Vs[2][GBM * LDP];
    __shared__ __align__(16) uint Ps[2][GBN * LDP];

    int tid  = threadIdx.x;      // 0..255
    int lane = tid & 31, wid = tid >> 5;
    int wm = (wid & 1) * 32;
    int wn = (wid >> 1) * 16;

    const uint* V = (const uint*)g_v    + (size_t)b * C * N;
    const uint* P = (const uint*)g_attn + (size_t)b * N * N;

    int crow = tid >> 3;
    int cf4  = (tid & 7) * 4;

    float acc[2][2][4];
#pragma unroll
    for (int am = 0; am < 2; am++)
#pragma unroll
        for (int an = 0; an < 2; an++)
#pragma unroll
            for (int j = 0; j < 4; j++) acc[am][an][j] = 0.f;

    int r4 = lane >> 2, q4 = lane & 3;

    {
#pragma unroll
        for (int i = 0; i < 2; i++) {
            int row = crow + i * 32;
            cp16((uint)__cvta_generic_to_shared(&Vs[0][row * LDP + cf4]),
                 V + (size_t)(c0 + row) * N + cf4);
            cp16((uint)__cvta_generic_to_shared(&Ps[0][row * LDP + cf4]),
                 P + (size_t)(n0 + row) * N + cf4);
        }
        asm volatile("cp.async.commit_group;");
    }

    for (int ch = 0; ch < NCHUNK; ch++) {
        int s = ch & 1;
        if (ch + 1 < NCHUNK) {
            int m1 = (ch + 1) * GBK;
#pragma unroll
            for (int i = 0; i < 2; i++) {
                int row = crow + i * 32;
                cp16((uint)__cvta_generic_to_shared(&Vs[s ^ 1][row * LDP + cf4]),
                     V + (size_t)(c0 + row) * N + m1 + cf4);
                cp16((uint)__cvta_generic_to_shared(&Ps[s ^ 1][row * LDP + cf4]),
                     P + (size_t)(n0 + row) * N + m1 + cf4);
            }
            asm volatile("cp.async.commit_group;");
            asm volatile("cp.async.wait_group 1;");
        } else {
            asm volatile("cp.async.wait_group 0;");
        }
        __syncthreads();

        const uint* Vss = Vs[s];
        const uint* Pss = Ps[s];
#pragma unroll
        for (int k8 = 0; k8 < GBK; k8 += 8) {
            uint a[2][4], bb[2][2];
#pragma unroll
            for (int am = 0; am < 2; am++) {
                uint2 a02 = *(const uint2*)&Vss[(wm + am * 16 + r4) * LDP + k8 + 2 * q4];
                uint2 a13 = *(const uint2*)&Vss[(wm + am * 16 + 8 + r4) * LDP + k8 + 2 * q4];
                a[am][0] = a02.x; a[am][2] = a02.y;
                a[am][1] = a13.x; a[am][3] = a13.y;
            }
#pragma unroll
            for (int an = 0; an < 2; an++) {
                uint2 bv = *(const uint2*)&Pss[(wn + an * 8 + r4) * LDP + k8 + 2 * q4];
                bb[an][0] = bv.x;
                bb[an][1] = bv.y;
            }
#pragma unroll
            for (int am = 0; am < 2; am++)
#pragma unroll
                for (int an = 0; an < 2; an++)
                    mma_tf32(acc[am][an], a[am], bb[an]);
        }
        __syncthreads();
    }

    // epilogue: output n-columns are NOT permuted (permutation was on contraction m)
    float* O = g_out + (size_t)b * C * N;
    const float* RS = g_rsum + (size_t)b * N;
    int cc = (lane & 3) * 2;
    float inv[2][2];
#pragma unroll
    for (int an = 0; an < 2; an++) {
        int nc = n0 + wn + an * 8 + cc;
        inv[an][0] = 1.0f / RS[nc];
        inv[an][1] = 1.0f / RS[nc + 1];
    }
#pragma unroll
    for (int am = 0; am < 2; am++)
#pragma unroll
        for (int an = 0; an < 2; an++) {
            int cr = c0 + wm + am * 16 + r4;
            int ncol = n0 + wn + an * 8 + cc;
            float2 lo; lo.x = acc[am][an][0] * inv[an][0]; lo.y = acc[am][an][1] * inv[an][1];
            float2 hi; hi.x = acc[am][an][2] * inv[an][0]; hi.y = acc[am][an][3] * inv[an][1];
            *(float2*)(O + (size_t)cr * N + ncol)       = lo;
            *(float2*)(O + (size_t)(cr + 8) * N + ncol) = hi;
        }
}

// ---------------- kernel 5: nearest 8x upsample + residual ----------------
__global__ void upsample_add_kernel(const float* __restrict__ f, float* __restrict__ out) {
    size_t idx = (size_t)blockIdx.x * blockDim.x + threadIdx.x;  // over B*C*H*W/4
    int w4 = (int)(idx & 63);
    int h  = (int)((idx >> 6) & 255);
    size_t bc = idx >> 14;
    int hp = h >> 3;
    int wp = w4 >> 1;
    float s = g_out[bc * N + (size_t)hp * WP + wp];
    float4 a = ((const float4*)f)[idx];
    a.x += s; a.y += s; a.z += s; a.w += s;
    ((float4*)out)[idx] = a;
}

// ---------------- launch ----------------
extern "C" void kernel_launch(void* const* d_in, const int* in_sizes, int n_in,
                              void* d_out, int out_size) {
    const float* f  = (const float*)d_in[0];
    const float* qw = (const float*)d_in[1];
    const float* qb = (const float*)d_in[2];
    const float* kw = (const float*)d_in[3];
    const float* kb = (const float*)d_in[4];
    const float* vw = (const float*)d_in[5];
    const float* vb = (const float*)d_in[6];
    float* out = (float*)d_out;

    avgpool_kernel<<<(BATCH * C * N) / 256, 256>>>(f);
    qkv_mma_kernel<<<dim3(N / 64, 5, BATCH), 256>>>(qw, qb, kw, kb, vw, vb);
    attn_mma_kernel<<<dim3(N / 16, BATCH), 256>>>();
    out_gemm_kernel<<<dim3(N / GBN, C / GBM, BATCH), 256>>>();
    upsample_add_kernel<<<(BATCH * C * H * (W / 4)) / 256, 256>>>(f, out);
}